// round 16
// baseline (speedup 1.0000x reference)
#include <cuda_runtime.h>
#include <cuda_fp16.h>
#include <cstdint>

#define NROWS 65536
#define BDIM  4096
#define HH    512
#define INF   64
#define DDIM  256
#define EK    320          // fused input K for emb GEMM (64 + 256)

// ---------------- scratch (static __device__ — no allocation APIs) ----------
__device__ float  g_traj_emb[BDIM * HH];                 // 8 MB  (f32)
__device__ __half g_traj_h[(size_t)BDIM * HH];           // 4 MB  (f16 traj)
__device__ __half g_x_h[(size_t)NROWS * EK];             // 40 MB (f16 packed neigh|dist)
__device__ __half g_wembT_h[(size_t)HH * EK];            // 320 KB (f16, [n][k] K-contig)
__device__ __half g_wembT2_h[(size_t)HH * HH];           // 512 KB (f16, rows 64:576 T)
__device__ __half g_emb_h[(size_t)NROWS * HH];           // 64 MB (f16)
__device__ __half g_ht_h[(size_t)NROWS * HH];            // 64 MB (f16)
__device__ __half g_wih_h[(size_t)3 * HH * HH];          // 1.5 MB
__device__ __half g_whh_h[(size_t)3 * HH * HH];          // 1.5 MB
__device__ int    g_sid[NROWS];

// ---------------- helpers ----------------------------------------------------
__device__ __forceinline__ uint32_t h2u(__half2 h) {
    uint32_t u;
    asm("mov.b32 %0, %1;" : "=r"(u) : "r"(*reinterpret_cast<uint32_t*>(&h)));
    return u;
}
__device__ __forceinline__ uint32_t smem_u32(const void* p) {
    uint32_t a;
    asm("{ .reg .u64 t; cvta.to.shared.u64 t, %1; cvt.u32.u64 %0, t; }" : "=r"(a) : "l"(p));
    return a;
}
#define SWZ128(o) ((o) ^ (((o) >> 3) & 0x70))

// ---------------- HMMA / cp.async primitives --------------------------------
__device__ __forceinline__ void ldsm4(uint32_t &r0, uint32_t &r1, uint32_t &r2,
                                      uint32_t &r3, uint32_t addr) {
    asm volatile("ldmatrix.sync.aligned.m8n8.x4.shared.b16 {%0,%1,%2,%3}, [%4];"
                 : "=r"(r0), "=r"(r1), "=r"(r2), "=r"(r3) : "r"(addr));
}
__device__ __forceinline__ void hmma(float (&d)[4], uint32_t a0, uint32_t a1,
                                     uint32_t a2, uint32_t a3, uint32_t b0, uint32_t b1) {
    asm volatile("mma.sync.aligned.m16n8k16.row.col.f32.f16.f16.f32 "
                 "{%0,%1,%2,%3}, {%4,%5,%6,%7}, {%8,%9}, {%0,%1,%2,%3};"
                 : "+f"(d[0]), "+f"(d[1]), "+f"(d[2]), "+f"(d[3])
                 : "r"(a0), "r"(a1), "r"(a2), "r"(a3), "r"(b0), "r"(b1));
}
__device__ __forceinline__ void cp16(uint32_t dst, const void* src) {
    asm volatile("cp.async.cg.shared.global [%0], [%1], 16;" :: "r"(dst), "l"(src));
}
__device__ __forceinline__ void cp_commit() {
    asm volatile("cp.async.commit_group;" ::: "memory");
}
template<int N>
__device__ __forceinline__ void cp_wait() {
    asm volatile("cp.async.wait_group %0;" :: "n"(N) : "memory");
}

// ---------------- merged prep kernel -----------------------------------------
#define PB0 32768           // ht cvt   (8,388,608 float4)
#define PB1 (PB0 + 10240)   // cvtx     (2,621,440 items)
#define PB2 (PB1 + 2048)    // traj cvt (524,288 float4)
#define PB3 (PB2 + 768)     // wih cvt  (196,608 float4)
#define PB4 (PB3 + 768)     // whh cvt  (196,608 float4)
#define PB5 (PB4 + 640)     // wembT    (163,840 items)
#define PB6 (PB5 + 1024)    // wembT2   (262,144 items)
#define PB7 (PB6 + 256)     // sid      (65,536 items)

__device__ __forceinline__ void cvt4(const float* __restrict__ src,
                                     __half* __restrict__ dst, int i) {
    float4 v = ((const float4*)src)[i];
    ((__half2*)dst)[2 * i]     = __floats2half2_rn(v.x, v.y);
    ((__half2*)dst)[2 * i + 1] = __floats2half2_rn(v.z, v.w);
}

__global__ __launch_bounds__(256)
void prep_kernel(const float* __restrict__ traj, const float* __restrict__ neigh,
                 const float* __restrict__ dist, const float* __restrict__ ht,
                 const float* __restrict__ W_emb,
                 const float* __restrict__ w_ih, const float* __restrict__ w_hh,
                 const int* __restrict__ starts,
                 __half* __restrict__ traj_h, __half* __restrict__ x_h,
                 __half* __restrict__ ht_h, __half* __restrict__ wembT,
                 __half* __restrict__ wembT2, __half* __restrict__ wih_h,
                 __half* __restrict__ whh_h, int* __restrict__ sid)
{
    const int b = blockIdx.x, t = threadIdx.x;

    if (b < PB0) {
        cvt4(ht, ht_h, b * 256 + t);
    } else if (b < PB1) {
        int idx = (b - PB0) * 256 + t;
        int row = idx / 40, c = idx % 40;
        const float* src = (c < 8) ? (neigh + (size_t)row * INF + c * 8)
                                   : (dist + (size_t)row * DDIM + (c - 8) * 8);
        float4 v0 = ((const float4*)src)[0];
        float4 v1 = ((const float4*)src)[1];
        uint4 o;
        o.x = h2u(__floats2half2_rn(v0.x, v0.y));
        o.y = h2u(__floats2half2_rn(v0.z, v0.w));
        o.z = h2u(__floats2half2_rn(v1.x, v1.y));
        o.w = h2u(__floats2half2_rn(v1.z, v1.w));
        ((uint4*)(x_h + (size_t)row * EK))[c] = o;
    } else if (b < PB2) {
        cvt4(traj, traj_h, (b - PB1) * 256 + t);
    } else if (b < PB3) {
        cvt4(w_ih, wih_h, (b - PB2) * 256 + t);
    } else if (b < PB4) {
        cvt4(w_hh, whh_h, (b - PB3) * 256 + t);
    } else if (b < PB5) {
        int idx = (b - PB4) * 256 + t;
        int n = idx / EK, k = idx % EK;
        int kr = (k < INF) ? k : (k + 512);
        wembT[idx] = __float2half(W_emb[(size_t)kr * HH + n]);
    } else if (b < PB6) {
        int idx = (b - PB5) * 256 + t;
        int n = idx / HH, k = idx % HH;
        wembT2[idx] = __float2half(W_emb[(size_t)(INF + k) * HH + n]);
    } else {
        int i = (b - PB6) * 256 + t;
        int lo = 0, hi = BDIM - 1;
        while (lo < hi) {
            int mid = (lo + hi + 1) >> 1;
            if (starts[mid] <= i) lo = mid; else hi = mid - 1;
        }
        sid[i] = lo;
    }
}

// ---------------- generic HMMA GEMM: C_f32[M, n-tile64] = A@B^T -------------
#define ES_STAGE 24576u
#define ES_BIAS  49152u
#define ES_SMEM  49472u

template<int KTOT>
__global__ __launch_bounds__(256, 1)
void h_gemm_kernel(const __half* __restrict__ Ah, const __half* __restrict__ Bw,
                   float* __restrict__ C)
{
    extern __shared__ char smem[];
    const uint32_t sb = smem_u32(smem);
    const int tid = threadIdx.x, wid = tid >> 5, lane = tid & 31;
    const int m0 = blockIdx.y * 128;
    const int j0 = blockIdx.x * 64;
    constexpr int NCH = KTOT / 64;

    float acc[8][4];
#pragma unroll
    for (int n = 0; n < 8; n++)
#pragma unroll
        for (int e = 0; e < 4; e++) acc[n][e] = 0.f;

    uint4 pf[6];
    auto fetch = [&](int kc) {
#pragma unroll
        for (int i = 0; i < 6; i++) {
            int u = i * 256 + tid;
            const __half* src = (u < 1024)
                ? (Ah + (size_t)(m0 + (u >> 3)) * KTOT + kc * 64 + (u & 7) * 8)
                : (Bw + (size_t)(j0 + ((u - 1024) >> 3)) * KTOT + kc * 64 + ((u - 1024) & 7) * 8);
            pf[i] = *(const uint4*)src;
        }
    };
    auto store = [&](int buf) {
        const uint32_t bb = sb + (uint32_t)buf * ES_STAGE;
#pragma unroll
        for (int i = 0; i < 6; i++) {
            int u = i * 256 + tid;
            uint32_t off = (u < 1024)
                ? SWZ128((uint32_t)((u >> 3) * 128 + (u & 7) * 16))
                : (16384u + SWZ128((uint32_t)((((u - 1024) >> 3)) * 128 + ((u - 1024) & 7) * 16)));
            asm volatile("st.shared.v4.b32 [%0], {%1,%2,%3,%4};"
                         :: "r"(bb + off), "r"(pf[i].x), "r"(pf[i].y),
                            "r"(pf[i].z), "r"(pf[i].w));
        }
    };

    const uint32_t arow = (uint32_t)((wid << 4) + (lane & 15)) * 128u + ((lane >> 4) << 4);
    const int brow = (lane & 7) + ((lane >> 4) << 3);
    const uint32_t bkoff = (uint32_t)(((lane >> 3) & 1) << 4);

    fetch(0); store(0); __syncthreads();

#pragma unroll 1
    for (int kc = 0; kc < NCH; kc++) {
        const int cur = kc & 1;
        if (kc < NCH - 1) fetch(kc + 1);

        const uint32_t base = sb + (uint32_t)cur * ES_STAGE;
#pragma unroll
        for (int ks = 0; ks < 4; ks++) {
            uint32_t a0, a1, a2, a3;
            ldsm4(a0, a1, a2, a3, base + SWZ128(arow + (uint32_t)ks * 32u));
#pragma unroll
            for (int nf2 = 0; nf2 < 4; nf2++) {
                uint32_t b0, b1, b2, b3;
                uint32_t ba = base + 16384u +
                    SWZ128((uint32_t)((nf2 * 16 + brow) * 128) + (uint32_t)ks * 32u + bkoff);
                ldsm4(b0, b1, b2, b3, ba);
                hmma(acc[nf2 * 2],     a0, a1, a2, a3, b0, b1);
                hmma(acc[nf2 * 2 + 1], a0, a1, a2, a3, b2, b3);
            }
        }

        if (kc < NCH - 1) { store(cur ^ 1); __syncthreads(); }
    }

    const int t4 = lane & 3, gid = lane >> 2;
    const int r0 = m0 + wid * 16 + gid;
#pragma unroll
    for (int nf = 0; nf < 8; nf++) {
        const int c = nf * 8 + 2 * t4;
        *(float2*)(C + (size_t)r0 * HH + j0 + c)       = make_float2(acc[nf][0], acc[nf][1]);
        *(float2*)(C + (size_t)(r0 + 8) * HH + j0 + c) = make_float2(acc[nf][2], acc[nf][3]);
    }
}

// ---------------- HMMA emb kernel: 512 thr, 4x4 warp grid, cp.async ---------
// Warp-de-phased k-slices: ks = (ksi + wn) & 3.
__global__ __launch_bounds__(512, 1)
void emb_mma_kernel(const __half* __restrict__ xh, const __half* __restrict__ wt,
                    const float* __restrict__ traj_emb, const float* __restrict__ bias,
                    const int* __restrict__ sid, __half* __restrict__ emb)
{
    extern __shared__ char smem[];
    const uint32_t sb = smem_u32(smem);
    const int tid = threadIdx.x, wid = tid >> 5, lane = tid & 31;
    const int wm = wid & 3, wn = wid >> 2;             // 4(m) x 4(n)
    const int m0 = blockIdx.y * 128;
    const int j0 = blockIdx.x * 64;

    float* bp = (float*)(smem + ES_BIAS);
    if (tid < 64) bp[tid] = bias[j0 + tid];

    float acc[2][2][4];                                // [mf][nfrag][e]
#pragma unroll
    for (int mf = 0; mf < 2; mf++)
#pragma unroll
        for (int nf = 0; nf < 2; nf++)
#pragma unroll
            for (int e = 0; e < 4; e++) acc[mf][nf][e] = 0.f;

    auto cp_issue = [&](int kc, int buf) {
        const uint32_t bb = sb + (uint32_t)buf * ES_STAGE;
#pragma unroll
        for (int i = 0; i < 3; i++) {
            int u = i * 512 + tid;                     // 0..1535 16B-units
            const __half* src;
            uint32_t off;
            if (u < 1024) {
                src = xh + (size_t)(m0 + (u >> 3)) * EK + kc * 64 + (u & 7) * 8;
                off = SWZ128((uint32_t)((u >> 3) * 128 + (u & 7) * 16));
            } else {
                int w = u - 1024;
                src = wt + (size_t)(j0 + (w >> 3)) * EK + kc * 64 + (w & 7) * 8;
                off = 16384u + SWZ128((uint32_t)((w >> 3) * 128 + (w & 7) * 16));
            }
            cp16(bb + off, src);
        }
        cp_commit();
    };

    uint32_t arowb[2];
#pragma unroll
    for (int mf = 0; mf < 2; mf++)
        arowb[mf] = (uint32_t)(wm * 32 + mf * 16 + (lane & 15)) * 128u + ((lane >> 4) << 4);
    const int brow = (lane & 7) + ((lane >> 4) << 3);
    const uint32_t bkoff = (uint32_t)(((lane >> 3) & 1) << 4);

    auto compute = [&](int buf) {
        const uint32_t abase = sb + (uint32_t)buf * ES_STAGE;
        const uint32_t bbase = abase + 16384u;
#pragma unroll
        for (int ksi = 0; ksi < 4; ksi++) {
            const int ks = (ksi + wn) & 3;             // de-phase warps per SMSP
            uint32_t a[2][4];
#pragma unroll
            for (int mf = 0; mf < 2; mf++)
                ldsm4(a[mf][0], a[mf][1], a[mf][2], a[mf][3],
                      abase + SWZ128(arowb[mf] + (uint32_t)ks * 32u));
            uint32_t b0, b1, b2, b3;
            uint32_t ba = bbase +
                SWZ128((uint32_t)((wn * 16 + brow) * 128) + (uint32_t)ks * 32u + bkoff);
            ldsm4(b0, b1, b2, b3, ba);
#pragma unroll
            for (int mf = 0; mf < 2; mf++) {
                hmma(acc[mf][0], a[mf][0], a[mf][1], a[mf][2], a[mf][3], b0, b1);
                hmma(acc[mf][1], a[mf][0], a[mf][1], a[mf][2], a[mf][3], b2, b3);
            }
        }
    };

    cp_issue(0, 0);
    cp_issue(1, 1);

#pragma unroll 1
    for (int kc = 0; kc < 5; kc++) {
        if (kc == 4) cp_wait<0>(); else cp_wait<1>();
        __syncthreads();
        compute(kc & 1);
        if (kc + 2 < 5) { __syncthreads(); cp_issue(kc + 2, kc & 1); }
    }

    // ---------------- epilogue: + traj_emb[sid] + bias, relu, f16 store -----
    const int t4 = lane & 3, gid = lane >> 2;
#pragma unroll
    for (int mf = 0; mf < 2; mf++) {
        const int r = m0 + wm * 32 + mf * 16 + gid;
        const int s0 = sid[r], s1 = sid[r + 8];
        const float* tp0 = traj_emb + (size_t)s0 * HH + j0;
        const float* tp1 = traj_emb + (size_t)s1 * HH + j0;
#pragma unroll
        for (int nf = 0; nf < 2; nf++) {
            const int cl = wn * 16 + nf * 8 + 2 * t4;
            float2 t0 = *(const float2*)(tp0 + cl);
            float2 t1 = *(const float2*)(tp1 + cl);
            float b0 = bp[cl], b1 = bp[cl + 1];
            float e00 = fmaxf(acc[mf][nf][0] + t0.x + b0, 0.f);
            float e01 = fmaxf(acc[mf][nf][1] + t0.y + b1, 0.f);
            float e10 = fmaxf(acc[mf][nf][2] + t1.x + b0, 0.f);
            float e11 = fmaxf(acc[mf][nf][3] + t1.y + b1, 0.f);
            *(__half2*)(emb + (size_t)r * HH + j0 + cl)       = __floats2half2_rn(e00, e01);
            *(__half2*)(emb + (size_t)(r + 8) * HH + j0 + cl) = __floats2half2_rn(e10, e11);
        }
    }
}

// ---------------- GRU gate math ---------------------------------------------
__device__ __forceinline__ float sigf(float x) { return 1.f / (1.f + __expf(-x)); }
__device__ __forceinline__ float tanhfast(float x) {
    float ax = fabsf(x);
    float e  = __expf(-2.f * ax);
    float t  = (1.f - e) / (1.f + e);
    return copysignf(t, x);
}
__device__ __forceinline__ float gru1(float sr, float sz, float i_n, float h_n, float h) {
    float r = sigf(sr);
    float z = sigf(sz);
    float n = tanhfast(i_n + r * h_n);
    return (1.f - z) * n + z * h;
}

// ---------------- fused HMMA kernel: gi/gh GEMMs + gates --------------------
// 512 threads, 4(m)x4(n) warp grid, double-wide cp.async stages,
// warp-de-phased k-slices (ks = (ksi + wn) & 3).
#define FG_STAGE 81920u
#define FG_BIAS  163840u
#define FG_SMEM  164864u

template<int PHASE>
__device__ __forceinline__ void gemm_phase(
    uint32_t sb, const __half* __restrict__ Asrc, const __half* __restrict__ Bsrc,
    int m0, int j0, int tid, int wm, int wn, int lane, float (&acc)[4][2][2][4])
{
    auto cp_issue = [&](int kc, int buf, int h) {
        const uint32_t bb = sb + (uint32_t)buf * FG_STAGE;
#pragma unroll
        for (int i = 0; i < 5; i++) {
            int u = i * 512 + tid;                      // 0..2559
            const __half* src;
            uint32_t off;
            if (u < 1024) {
                src = Asrc + (size_t)(m0 + (u >> 3)) * 512 + kc * 64 + (u & 7) * 8;
                off = (uint32_t)h * 16384u +
                      SWZ128((uint32_t)((u >> 3) * 128 + (u & 7) * 16));
            } else {
                int v = u - 1024, g = v >> 9, w = v & 511;
                src = Bsrc + (size_t)(g * 512 + j0 + (w >> 3)) * 512 + kc * 64 + (w & 7) * 8;
                off = 32768u + (uint32_t)h * 24576u + (uint32_t)g * 8192u +
                      SWZ128((uint32_t)((w >> 3) * 128 + (w & 7) * 16));
            }
            cp16(bb + off, src);
        }
        cp_commit();
    };

    uint32_t arowb[2];
#pragma unroll
    for (int mf = 0; mf < 2; mf++)
        arowb[mf] = (uint32_t)(wm * 32 + mf * 16 + (lane & 15)) * 128u + ((lane >> 4) << 4);
    const int brow = (lane & 7) + ((lane >> 4) << 3);
    const uint32_t bkoff = (uint32_t)(((lane >> 3) & 1) << 4);

    auto computeh = [&](int buf, int h) {
        const uint32_t abase = sb + (uint32_t)buf * FG_STAGE + (uint32_t)h * 16384u;
        const uint32_t bbase = sb + (uint32_t)buf * FG_STAGE + 32768u + (uint32_t)h * 24576u;
#pragma unroll
        for (int ksi = 0; ksi < 4; ksi++) {
            const int ks = (ksi + wn) & 3;             // de-phase warps per SMSP
            uint32_t a[2][4];
#pragma unroll
            for (int mf = 0; mf < 2; mf++)
                ldsm4(a[mf][0], a[mf][1], a[mf][2], a[mf][3],
                      abase + SWZ128(arowb[mf] + (uint32_t)ks * 32u));
#pragma unroll
            for (int g = 0; g < 3; g++) {
                const int grp = (g < 2) ? g : (2 + PHASE);
                uint32_t b0, b1, b2, b3;
                uint32_t ba = bbase + (uint32_t)g * 8192u +
                    SWZ128((uint32_t)((wn * 16 + brow) * 128) +
                           (uint32_t)ks * 32u + bkoff);
                ldsm4(b0, b1, b2, b3, ba);
#pragma unroll
                for (int mf = 0; mf < 2; mf++) {
                    hmma(acc[grp][mf][0],
                         a[mf][0], a[mf][1], a[mf][2], a[mf][3], b0, b1);
                    hmma(acc[grp][mf][1],
                         a[mf][0], a[mf][1], a[mf][2], a[mf][3], b2, b3);
                }
            }
        }
    };

    cp_issue(0, 0, 0);
    cp_issue(1, 0, 1);
    cp_wait<0>();
    __syncthreads();

#pragma unroll 1
    for (int dc = 0; dc < 4; dc++) {
        const int cur = dc & 1;
        if (dc < 3) {
            cp_issue(2 * dc + 2, cur ^ 1, 0);
            cp_issue(2 * dc + 3, cur ^ 1, 1);
        }
        computeh(cur, 0);
        computeh(cur, 1);
        if (dc < 3) cp_wait<0>();
        __syncthreads();
    }
}

__global__ __launch_bounds__(512, 1)
void fused_gru_kernel(const __half* __restrict__ emb_h, const __half* __restrict__ ht_h,
                      const __half* __restrict__ wih_h, const __half* __restrict__ whh_h,
                      const float* __restrict__ ht,
                      const float* __restrict__ b_ih, const float* __restrict__ b_hh,
                      float* __restrict__ out)
{
    extern __shared__ char smem[];
    const uint32_t sb = smem_u32(smem);
    const int tid = threadIdx.x, wid = tid >> 5, lane = tid & 31;
    const int wm = wid & 3, wn = wid >> 2;             // 4(m) x 4(n)
    const int m0 = blockIdx.y * 128;
    const int j0 = blockIdx.x * 64;

    float* bp = (float*)(smem + FG_BIAS);
    if (tid < 64) {
        int j = j0 + tid;
        bp[tid]       = b_ih[j]        + b_hh[j];
        bp[64 + tid]  = b_ih[512 + j]  + b_hh[512 + j];
        bp[128 + tid] = b_ih[1024 + j];
        bp[192 + tid] = b_hh[1024 + j];
    }

    float acc[4][2][2][4];                             // [slot][mf][nfrag][e]
#pragma unroll
    for (int s = 0; s < 4; s++)
#pragma unroll
        for (int mf = 0; mf < 2; mf++)
#pragma unroll
            for (int nf = 0; nf < 2; nf++)
#pragma unroll
                for (int e = 0; e < 4; e++) acc[s][mf][nf][e] = 0.f;

    gemm_phase<0>(sb, emb_h, wih_h, m0, j0, tid, wm, wn, lane, acc);
    gemm_phase<1>(sb, ht_h, whh_h, m0, j0, tid, wm, wn, lane, acc);

    const int t4 = lane & 3, gid = lane >> 2;
#pragma unroll
    for (int mf = 0; mf < 2; mf++) {
        const int r = m0 + wm * 32 + mf * 16 + gid;
#pragma unroll
        for (int nf = 0; nf < 2; nf++) {
            const int cl = wn * 16 + nf * 8 + 2 * t4;
            const float* hp0 = ht + (size_t)r * HH + j0 + cl;
            const float* hp1 = hp0 + 8 * HH;
            float2 h0 = *(const float2*)hp0;
            float2 h1 = *(const float2*)hp1;

            float2 o0, o1;
            o0.x = gru1(acc[0][mf][nf][0] + bp[cl],     acc[1][mf][nf][0] + bp[64 + cl],
                        acc[2][mf][nf][0] + bp[128 + cl], acc[3][mf][nf][0] + bp[192 + cl], h0.x);
            o0.y = gru1(acc[0][mf][nf][1] + bp[cl + 1], acc[1][mf][nf][1] + bp[64 + cl + 1],
                        acc[2][mf][nf][1] + bp[128 + cl + 1], acc[3][mf][nf][1] + bp[192 + cl + 1], h0.y);
            o1.x = gru1(acc[0][mf][nf][2] + bp[cl],     acc[1][mf][nf][2] + bp[64 + cl],
                        acc[2][mf][nf][2] + bp[128 + cl], acc[3][mf][nf][2] + bp[192 + cl], h1.x);
            o1.y = gru1(acc[0][mf][nf][3] + bp[cl + 1], acc[1][mf][nf][3] + bp[64 + cl + 1],
                        acc[2][mf][nf][3] + bp[128 + cl + 1], acc[3][mf][nf][3] + bp[192 + cl + 1], h1.y);

            *(float2*)(out + (size_t)r * HH + j0 + cl)       = o0;
            *(float2*)(out + (size_t)(r + 8) * HH + j0 + cl) = o1;
        }
    }
}

// ---------------- launch ----------------------------------------------------
extern "C" void kernel_launch(void* const* d_in, const int* in_sizes, int n_in,
                              void* d_out, int out_size)
{
    const float* traj  = (const float*)d_in[0];
    const float* neigh = (const float*)d_in[1];
    const float* dist  = (const float*)d_in[2];
    const float* ht    = (const float*)d_in[3];
    const float* W_emb = (const float*)d_in[4];
    const float* b_emb = (const float*)d_in[5];
    const float* w_ih  = (const float*)d_in[6];
    const float* w_hh  = (const float*)d_in[7];
    const float* b_ih  = (const float*)d_in[8];
    const float* b_hh  = (const float*)d_in[9];
    const int*   starts = (const int*)d_in[10];
    float* out = (float*)d_out;

    float *p_traj_emb;
    __half *p_traj_h, *p_x_h, *p_wembT_h, *p_wembT2_h, *p_emb_h, *p_ht_h, *p_wih_h, *p_whh_h;
    int* p_sid;
    cudaGetSymbolAddress((void**)&p_traj_emb, g_traj_emb);
    cudaGetSymbolAddress((void**)&p_traj_h, g_traj_h);
    cudaGetSymbolAddress((void**)&p_x_h, g_x_h);
    cudaGetSymbolAddress((void**)&p_wembT_h, g_wembT_h);
    cudaGetSymbolAddress((void**)&p_wembT2_h, g_wembT2_h);
    cudaGetSymbolAddress((void**)&p_emb_h, g_emb_h);
    cudaGetSymbolAddress((void**)&p_ht_h, g_ht_h);
    cudaGetSymbolAddress((void**)&p_wih_h, g_wih_h);
    cudaGetSymbolAddress((void**)&p_whh_h, g_whh_h);
    cudaGetSymbolAddress((void**)&p_sid, g_sid);

    cudaFuncSetAttribute(fused_gru_kernel,
                         cudaFuncAttributeMaxDynamicSharedMemorySize, FG_SMEM);
    cudaFuncSetAttribute(emb_mma_kernel,
                         cudaFuncAttributeMaxDynamicSharedMemorySize, ES_SMEM);
    cudaFuncSetAttribute(h_gemm_kernel<512>,
                         cudaFuncAttributeMaxDynamicSharedMemorySize, ES_SMEM);

    // 1) merged prep (one launch)
    prep_kernel<<<PB7, 256>>>(traj, neigh, dist, ht, W_emb, w_ih, w_hh, starts,
                              p_traj_h, p_x_h, p_ht_h, p_wembT_h, p_wembT2_h,
                              p_wih_h, p_whh_h, p_sid);

    // 2) traj_emb(f32) = traj @ W_emb[64:576]   [HMMA]
    h_gemm_kernel<512><<<dim3(HH / 64, BDIM / 128), 256, ES_SMEM>>>(
        p_traj_h, p_wembT2_h, p_traj_emb);

    // 3) emb(f16) = relu(X @ WembT^T + traj_emb[sid] + b_emb)  [HMMA, 512 thr]
    emb_mma_kernel<<<dim3(HH / 64, NROWS / 128), 512, ES_SMEM>>>(
        p_x_h, p_wembT_h, p_traj_emb, b_emb, p_sid, p_emb_h);

    // 4) fused: gi/gh GEMMs (HMMA, de-phased warps, cp.async) + gates
    fused_gru_kernel<<<dim3(HH / 64, NROWS / 128), 512, FG_SMEM>>>(
        p_emb_h, p_ht_h, p_wih_h, p_whh_h, ht, b_ih, b_hh, out);
}

// round 17
// speedup vs baseline: 1.0022x; 1.0022x over previous
#include <cuda_runtime.h>
#include <cuda_fp16.h>
#include <cstdint>

#define NROWS 65536
#define BDIM  4096
#define HH    512
#define INF   64
#define DDIM  256
#define EK    320          // fused input K for emb GEMM (64 + 256)

// ---------------- scratch (static __device__ — no allocation APIs) ----------
__device__ float  g_traj_emb[BDIM * HH];                 // 8 MB  (f32)
__device__ __half g_traj_h[(size_t)BDIM * HH];           // 4 MB  (f16 traj)
__device__ __half g_x_h[(size_t)NROWS * EK];             // 40 MB (f16 packed neigh|dist)
__device__ __half g_wembT_h[(size_t)HH * EK];            // 320 KB (f16, [n][k] K-contig)
__device__ __half g_wembT2_h[(size_t)HH * HH];           // 512 KB (f16, rows 64:576 T)
__device__ __half g_emb_h[(size_t)NROWS * HH];           // 64 MB (f16)
__device__ __half g_ht_h[(size_t)NROWS * HH];            // 64 MB (f16)
__device__ __half g_wih_h[(size_t)3 * HH * HH];          // 1.5 MB
__device__ __half g_whh_h[(size_t)3 * HH * HH];          // 1.5 MB
__device__ int    g_sid[NROWS];

// ---------------- helpers ----------------------------------------------------
__device__ __forceinline__ uint32_t h2u(__half2 h) {
    uint32_t u;
    asm("mov.b32 %0, %1;" : "=r"(u) : "r"(*reinterpret_cast<uint32_t*>(&h)));
    return u;
}
__device__ __forceinline__ uint32_t smem_u32(const void* p) {
    uint32_t a;
    asm("{ .reg .u64 t; cvta.to.shared.u64 t, %1; cvt.u32.u64 %0, t; }" : "=r"(a) : "l"(p));
    return a;
}
#define SWZ128(o) ((o) ^ (((o) >> 3) & 0x70))

// ---------------- HMMA / cp.async primitives --------------------------------
__device__ __forceinline__ void ldsm4(uint32_t &r0, uint32_t &r1, uint32_t &r2,
                                      uint32_t &r3, uint32_t addr) {
    asm volatile("ldmatrix.sync.aligned.m8n8.x4.shared.b16 {%0,%1,%2,%3}, [%4];"
                 : "=r"(r0), "=r"(r1), "=r"(r2), "=r"(r3) : "r"(addr));
}
__device__ __forceinline__ void hmma(float (&d)[4], uint32_t a0, uint32_t a1,
                                     uint32_t a2, uint32_t a3, uint32_t b0, uint32_t b1) {
    asm volatile("mma.sync.aligned.m16n8k16.row.col.f32.f16.f16.f32 "
                 "{%0,%1,%2,%3}, {%4,%5,%6,%7}, {%8,%9}, {%0,%1,%2,%3};"
                 : "+f"(d[0]), "+f"(d[1]), "+f"(d[2]), "+f"(d[3])
                 : "r"(a0), "r"(a1), "r"(a2), "r"(a3), "r"(b0), "r"(b1));
}
__device__ __forceinline__ void cp16(uint32_t dst, const void* src) {
    asm volatile("cp.async.cg.shared.global [%0], [%1], 16;" :: "r"(dst), "l"(src));
}
__device__ __forceinline__ void cp_commit() {
    asm volatile("cp.async.commit_group;" ::: "memory");
}
template<int N>
__device__ __forceinline__ void cp_wait() {
    asm volatile("cp.async.wait_group %0;" :: "n"(N) : "memory");
}

// ---------------- merged prep kernel -----------------------------------------
#define PB0 32768           // ht cvt   (8,388,608 float4)
#define PB1 (PB0 + 10240)   // cvtx     (2,621,440 items)
#define PB2 (PB1 + 2048)    // traj cvt (524,288 float4)
#define PB3 (PB2 + 768)     // wih cvt  (196,608 float4)
#define PB4 (PB3 + 768)     // whh cvt  (196,608 float4)
#define PB5 (PB4 + 640)     // wembT    (163,840 items)
#define PB6 (PB5 + 1024)    // wembT2   (262,144 items)
#define PB7 (PB6 + 256)     // sid      (65,536 items)

__device__ __forceinline__ void cvt4(const float* __restrict__ src,
                                     __half* __restrict__ dst, int i) {
    float4 v = ((const float4*)src)[i];
    ((__half2*)dst)[2 * i]     = __floats2half2_rn(v.x, v.y);
    ((__half2*)dst)[2 * i + 1] = __floats2half2_rn(v.z, v.w);
}

__global__ __launch_bounds__(256)
void prep_kernel(const float* __restrict__ traj, const float* __restrict__ neigh,
                 const float* __restrict__ dist, const float* __restrict__ ht,
                 const float* __restrict__ W_emb,
                 const float* __restrict__ w_ih, const float* __restrict__ w_hh,
                 const int* __restrict__ starts,
                 __half* __restrict__ traj_h, __half* __restrict__ x_h,
                 __half* __restrict__ ht_h, __half* __restrict__ wembT,
                 __half* __restrict__ wembT2, __half* __restrict__ wih_h,
                 __half* __restrict__ whh_h, int* __restrict__ sid)
{
    const int b = blockIdx.x, t = threadIdx.x;

    if (b < PB0) {
        cvt4(ht, ht_h, b * 256 + t);
    } else if (b < PB1) {
        int idx = (b - PB0) * 256 + t;
        int row = idx / 40, c = idx % 40;
        const float* src = (c < 8) ? (neigh + (size_t)row * INF + c * 8)
                                   : (dist + (size_t)row * DDIM + (c - 8) * 8);
        float4 v0 = ((const float4*)src)[0];
        float4 v1 = ((const float4*)src)[1];
        uint4 o;
        o.x = h2u(__floats2half2_rn(v0.x, v0.y));
        o.y = h2u(__floats2half2_rn(v0.z, v0.w));
        o.z = h2u(__floats2half2_rn(v1.x, v1.y));
        o.w = h2u(__floats2half2_rn(v1.z, v1.w));
        ((uint4*)(x_h + (size_t)row * EK))[c] = o;
    } else if (b < PB2) {
        cvt4(traj, traj_h, (b - PB1) * 256 + t);
    } else if (b < PB3) {
        cvt4(w_ih, wih_h, (b - PB2) * 256 + t);
    } else if (b < PB4) {
        cvt4(w_hh, whh_h, (b - PB3) * 256 + t);
    } else if (b < PB5) {
        int idx = (b - PB4) * 256 + t;
        int n = idx / EK, k = idx % EK;
        int kr = (k < INF) ? k : (k + 512);
        wembT[idx] = __float2half(W_emb[(size_t)kr * HH + n]);
    } else if (b < PB6) {
        int idx = (b - PB5) * 256 + t;
        int n = idx / HH, k = idx % HH;
        wembT2[idx] = __float2half(W_emb[(size_t)(INF + k) * HH + n]);
    } else {
        int i = (b - PB6) * 256 + t;
        int lo = 0, hi = BDIM - 1;
        while (lo < hi) {
            int mid = (lo + hi + 1) >> 1;
            if (starts[mid] <= i) lo = mid; else hi = mid - 1;
        }
        sid[i] = lo;
    }
}

// ---------------- generic HMMA GEMM: C_f32[M, n-tile64] = A@B^T -------------
#define ES_STAGE 24576u
#define ES_SMEM  49472u

template<int KTOT>
__global__ __launch_bounds__(256, 1)
void h_gemm_kernel(const __half* __restrict__ Ah, const __half* __restrict__ Bw,
                   float* __restrict__ C)
{
    extern __shared__ char smem[];
    const uint32_t sb = smem_u32(smem);
    const int tid = threadIdx.x, wid = tid >> 5, lane = tid & 31;
    const int m0 = blockIdx.y * 128;
    const int j0 = blockIdx.x * 64;
    constexpr int NCH = KTOT / 64;

    float acc[8][4];
#pragma unroll
    for (int n = 0; n < 8; n++)
#pragma unroll
        for (int e = 0; e < 4; e++) acc[n][e] = 0.f;

    uint4 pf[6];
    auto fetch = [&](int kc) {
#pragma unroll
        for (int i = 0; i < 6; i++) {
            int u = i * 256 + tid;
            const __half* src = (u < 1024)
                ? (Ah + (size_t)(m0 + (u >> 3)) * KTOT + kc * 64 + (u & 7) * 8)
                : (Bw + (size_t)(j0 + ((u - 1024) >> 3)) * KTOT + kc * 64 + ((u - 1024) & 7) * 8);
            pf[i] = *(const uint4*)src;
        }
    };
    auto store = [&](int buf) {
        const uint32_t bb = sb + (uint32_t)buf * ES_STAGE;
#pragma unroll
        for (int i = 0; i < 6; i++) {
            int u = i * 256 + tid;
            uint32_t off = (u < 1024)
                ? SWZ128((uint32_t)((u >> 3) * 128 + (u & 7) * 16))
                : (16384u + SWZ128((uint32_t)((((u - 1024) >> 3)) * 128 + ((u - 1024) & 7) * 16)));
            asm volatile("st.shared.v4.b32 [%0], {%1,%2,%3,%4};"
                         :: "r"(bb + off), "r"(pf[i].x), "r"(pf[i].y),
                            "r"(pf[i].z), "r"(pf[i].w));
        }
    };

    const uint32_t arow = (uint32_t)((wid << 4) + (lane & 15)) * 128u + ((lane >> 4) << 4);
    const int brow = (lane & 7) + ((lane >> 4) << 3);
    const uint32_t bkoff = (uint32_t)(((lane >> 3) & 1) << 4);

    fetch(0); store(0); __syncthreads();

#pragma unroll 1
    for (int kc = 0; kc < NCH; kc++) {
        const int cur = kc & 1;
        if (kc < NCH - 1) fetch(kc + 1);

        const uint32_t base = sb + (uint32_t)cur * ES_STAGE;
#pragma unroll
        for (int ks = 0; ks < 4; ks++) {
            uint32_t a0, a1, a2, a3;
            ldsm4(a0, a1, a2, a3, base + SWZ128(arow + (uint32_t)ks * 32u));
#pragma unroll
            for (int nf2 = 0; nf2 < 4; nf2++) {
                uint32_t b0, b1, b2, b3;
                uint32_t ba = base + 16384u +
                    SWZ128((uint32_t)((nf2 * 16 + brow) * 128) + (uint32_t)ks * 32u + bkoff);
                ldsm4(b0, b1, b2, b3, ba);
                hmma(acc[nf2 * 2],     a0, a1, a2, a3, b0, b1);
                hmma(acc[nf2 * 2 + 1], a0, a1, a2, a3, b2, b3);
            }
        }

        if (kc < NCH - 1) { store(cur ^ 1); __syncthreads(); }
    }

    const int t4 = lane & 3, gid = lane >> 2;
    const int r0 = m0 + wid * 16 + gid;
#pragma unroll
    for (int nf = 0; nf < 8; nf++) {
        const int c = nf * 8 + 2 * t4;
        *(float2*)(C + (size_t)r0 * HH + j0 + c)       = make_float2(acc[nf][0], acc[nf][1]);
        *(float2*)(C + (size_t)(r0 + 8) * HH + j0 + c) = make_float2(acc[nf][2], acc[nf][3]);
    }
}

// ---------------- HMMA emb kernel: 512 thr, 3-stage cp.async, 1 sync/chunk --
#define EM_STAGE 24576u
#define EM_BIAS  73728u
#define EM_SMEM  73984u

__global__ __launch_bounds__(512, 1)
void emb_mma_kernel(const __half* __restrict__ xh, const __half* __restrict__ wt,
                    const float* __restrict__ traj_emb, const float* __restrict__ bias,
                    const int* __restrict__ sid, __half* __restrict__ emb)
{
    extern __shared__ char smem[];
    const uint32_t sb = smem_u32(smem);
    const int tid = threadIdx.x, wid = tid >> 5, lane = tid & 31;
    const int wm = wid & 3, wn = wid >> 2;             // 4(m) x 4(n)
    const int m0 = blockIdx.y * 128;
    const int j0 = blockIdx.x * 64;

    float* bp = (float*)(smem + EM_BIAS);
    if (tid < 64) bp[tid] = bias[j0 + tid];

    float acc[2][2][4];                                // [mf][nfrag][e]
#pragma unroll
    for (int mf = 0; mf < 2; mf++)
#pragma unroll
        for (int nf = 0; nf < 2; nf++)
#pragma unroll
            for (int e = 0; e < 4; e++) acc[mf][nf][e] = 0.f;

    auto cp_issue = [&](int kc, int st) {
        const uint32_t bb = sb + (uint32_t)st * EM_STAGE;
#pragma unroll
        for (int i = 0; i < 3; i++) {
            int u = i * 512 + tid;                     // 0..1535 16B-units
            const __half* src;
            uint32_t off;
            if (u < 1024) {
                src = xh + (size_t)(m0 + (u >> 3)) * EK + kc * 64 + (u & 7) * 8;
                off = SWZ128((uint32_t)((u >> 3) * 128 + (u & 7) * 16));
            } else {
                int w = u - 1024;
                src = wt + (size_t)(j0 + (w >> 3)) * EK + kc * 64 + (w & 7) * 8;
                off = 16384u + SWZ128((uint32_t)((w >> 3) * 128 + (w & 7) * 16));
            }
            cp16(bb + off, src);
        }
        cp_commit();
    };

    uint32_t arowb[2];
#pragma unroll
    for (int mf = 0; mf < 2; mf++)
        arowb[mf] = (uint32_t)(wm * 32 + mf * 16 + (lane & 15)) * 128u + ((lane >> 4) << 4);
    const int brow = (lane & 7) + ((lane >> 4) << 3);
    const uint32_t bkoff = (uint32_t)(((lane >> 3) & 1) << 4);

    auto compute = [&](int st) {
        const uint32_t abase = sb + (uint32_t)st * EM_STAGE;
        const uint32_t bbase = abase + 16384u;
#pragma unroll
        for (int ksi = 0; ksi < 4; ksi++) {
            const int ks = (ksi + wn) & 3;
            uint32_t a[2][4];
#pragma unroll
            for (int mf = 0; mf < 2; mf++)
                ldsm4(a[mf][0], a[mf][1], a[mf][2], a[mf][3],
                      abase + SWZ128(arowb[mf] + (uint32_t)ks * 32u));
            uint32_t b0, b1, b2, b3;
            uint32_t ba = bbase +
                SWZ128((uint32_t)((wn * 16 + brow) * 128) + (uint32_t)ks * 32u + bkoff);
            ldsm4(b0, b1, b2, b3, ba);
#pragma unroll
            for (int mf = 0; mf < 2; mf++) {
                hmma(acc[mf][0], a[mf][0], a[mf][1], a[mf][2], a[mf][3], b0, b1);
                hmma(acc[mf][1], a[mf][0], a[mf][1], a[mf][2], a[mf][3], b2, b3);
            }
        }
    };

    cp_issue(0, 0);
    cp_issue(1, 1);

#pragma unroll 1
    for (int kc = 0; kc < 5; kc++) {
        if (kc == 4) cp_wait<0>(); else cp_wait<1>();
        __syncthreads();
        if (kc + 2 <= 4) cp_issue(kc + 2, (kc + 2) % 3);
        compute(kc % 3);
    }

    // ---------------- epilogue: + traj_emb[sid] + bias, relu, f16 store -----
    const int t4 = lane & 3, gid = lane >> 2;
#pragma unroll
    for (int mf = 0; mf < 2; mf++) {
        const int r = m0 + wm * 32 + mf * 16 + gid;
        const int s0 = sid[r], s1 = sid[r + 8];
        const float* tp0 = traj_emb + (size_t)s0 * HH + j0;
        const float* tp1 = traj_emb + (size_t)s1 * HH + j0;
#pragma unroll
        for (int nf = 0; nf < 2; nf++) {
            const int cl = wn * 16 + nf * 8 + 2 * t4;
            float2 t0 = *(const float2*)(tp0 + cl);
            float2 t1 = *(const float2*)(tp1 + cl);
            float b0 = bp[cl], b1 = bp[cl + 1];
            float e00 = fmaxf(acc[mf][nf][0] + t0.x + b0, 0.f);
            float e01 = fmaxf(acc[mf][nf][1] + t0.y + b1, 0.f);
            float e10 = fmaxf(acc[mf][nf][2] + t1.x + b0, 0.f);
            float e11 = fmaxf(acc[mf][nf][3] + t1.y + b1, 0.f);
            *(__half2*)(emb + (size_t)r * HH + j0 + cl)       = __floats2half2_rn(e00, e01);
            *(__half2*)(emb + (size_t)(r + 8) * HH + j0 + cl) = __floats2half2_rn(e10, e11);
        }
    }
}

// ---------------- GRU gate math ---------------------------------------------
__device__ __forceinline__ float sigf(float x) { return 1.f / (1.f + __expf(-x)); }
__device__ __forceinline__ float tanhfast(float x) {
    float ax = fabsf(x);
    float e  = __expf(-2.f * ax);
    float t  = (1.f - e) / (1.f + e);
    return copysignf(t, x);
}
__device__ __forceinline__ float gru1(float sr, float sz, float i_n, float h_n, float h) {
    float r = sigf(sr);
    float z = sigf(sz);
    float n = tanhfast(i_n + r * h_n);
    return (1.f - z) * n + z * h;
}

// ---------------- fused HMMA kernel: gi/gh GEMMs + gates --------------------
// 512 threads, 4(m)x4(n) warp grid, double-wide cp.async stages.
// Per k-slice: ALL 5 ldsm batched (MLP), then 12 independent hmma.
#define FG_STAGE 81920u
#define FG_BIAS  163840u
#define FG_SMEM  164864u

template<int PHASE>
__device__ __forceinline__ void gemm_phase(
    uint32_t sb, const __half* __restrict__ Asrc, const __half* __restrict__ Bsrc,
    int m0, int j0, int tid, int wm, int wn, int lane, float (&acc)[4][2][2][4])
{
    auto cp_issue = [&](int kc, int buf, int h) {
        const uint32_t bb = sb + (uint32_t)buf * FG_STAGE;
#pragma unroll
        for (int i = 0; i < 5; i++) {
            int u = i * 512 + tid;                      // 0..2559
            const __half* src;
            uint32_t off;
            if (u < 1024) {
                src = Asrc + (size_t)(m0 + (u >> 3)) * 512 + kc * 64 + (u & 7) * 8;
                off = (uint32_t)h * 16384u +
                      SWZ128((uint32_t)((u >> 3) * 128 + (u & 7) * 16));
            } else {
                int v = u - 1024, g = v >> 9, w = v & 511;
                src = Bsrc + (size_t)(g * 512 + j0 + (w >> 3)) * 512 + kc * 64 + (w & 7) * 8;
                off = 32768u + (uint32_t)h * 24576u + (uint32_t)g * 8192u +
                      SWZ128((uint32_t)((w >> 3) * 128 + (w & 7) * 16));
            }
            cp16(bb + off, src);
        }
        cp_commit();
    };

    uint32_t arowb[2];
#pragma unroll
    for (int mf = 0; mf < 2; mf++)
        arowb[mf] = (uint32_t)(wm * 32 + mf * 16 + (lane & 15)) * 128u + ((lane >> 4) << 4);
    const int brow = (lane & 7) + ((lane >> 4) << 3);
    const uint32_t bkoff = (uint32_t)(((lane >> 3) & 1) << 4);

    auto computeh = [&](int buf, int h) {
        const uint32_t abase = sb + (uint32_t)buf * FG_STAGE + (uint32_t)h * 16384u;
        const uint32_t bbase = sb + (uint32_t)buf * FG_STAGE + 32768u + (uint32_t)h * 24576u;
#pragma unroll
        for (int ksi = 0; ksi < 4; ksi++) {
            const int ks = (ksi + wn) & 3;
            // ---- batch all loads (MLP) ----
            uint32_t a[2][4];
#pragma unroll
            for (int mf = 0; mf < 2; mf++)
                ldsm4(a[mf][0], a[mf][1], a[mf][2], a[mf][3],
                      abase + SWZ128(arowb[mf] + (uint32_t)ks * 32u));
            uint32_t b[3][4];
#pragma unroll
            for (int g = 0; g < 3; g++)
                ldsm4(b[g][0], b[g][1], b[g][2], b[g][3],
                      bbase + (uint32_t)g * 8192u +
                      SWZ128((uint32_t)((wn * 16 + brow) * 128) +
                             (uint32_t)ks * 32u + bkoff));
            // ---- 12 independent hmma ----
#pragma unroll
            for (int g = 0; g < 3; g++) {
                const int grp = (g < 2) ? g : (2 + PHASE);
#pragma unroll
                for (int mf = 0; mf < 2; mf++) {
                    hmma(acc[grp][mf][0],
                         a[mf][0], a[mf][1], a[mf][2], a[mf][3], b[g][0], b[g][1]);
                    hmma(acc[grp][mf][1],
                         a[mf][0], a[mf][1], a[mf][2], a[mf][3], b[g][2], b[g][3]);
                }
            }
        }
    };

    cp_issue(0, 0, 0);
    cp_issue(1, 0, 1);
    cp_wait<0>();
    __syncthreads();

#pragma unroll 1
    for (int dc = 0; dc < 4; dc++) {
        const int cur = dc & 1;
        if (dc < 3) {
            cp_issue(2 * dc + 2, cur ^ 1, 0);
            cp_issue(2 * dc + 3, cur ^ 1, 1);
        }
        computeh(cur, 0);
        computeh(cur, 1);
        if (dc < 3) cp_wait<0>();
        __syncthreads();
    }
}

__global__ __launch_bounds__(512, 1)
void fused_gru_kernel(const __half* __restrict__ emb_h, const __half* __restrict__ ht_h,
                      const __half* __restrict__ wih_h, const __half* __restrict__ whh_h,
                      const float* __restrict__ ht,
                      const float* __restrict__ b_ih, const float* __restrict__ b_hh,
                      float* __restrict__ out)
{
    extern __shared__ char smem[];
    const uint32_t sb = smem_u32(smem);
    const int tid = threadIdx.x, wid = tid >> 5, lane = tid & 31;
    const int wm = wid & 3, wn = wid >> 2;             // 4(m) x 4(n)
    const int m0 = blockIdx.y * 128;
    const int j0 = blockIdx.x * 64;

    float* bp = (float*)(smem + FG_BIAS);
    if (tid < 64) {
        int j = j0 + tid;
        bp[tid]       = b_ih[j]        + b_hh[j];
        bp[64 + tid]  = b_ih[512 + j]  + b_hh[512 + j];
        bp[128 + tid] = b_ih[1024 + j];
        bp[192 + tid] = b_hh[1024 + j];
    }

    float acc[4][2][2][4];                             // [slot][mf][nfrag][e]
#pragma unroll
    for (int s = 0; s < 4; s++)
#pragma unroll
        for (int mf = 0; mf < 2; mf++)
#pragma unroll
            for (int nf = 0; nf < 2; nf++)
#pragma unroll
                for (int e = 0; e < 4; e++) acc[s][mf][nf][e] = 0.f;

    gemm_phase<0>(sb, emb_h, wih_h, m0, j0, tid, wm, wn, lane, acc);
    gemm_phase<1>(sb, ht_h, whh_h, m0, j0, tid, wm, wn, lane, acc);

    const int t4 = lane & 3, gid = lane >> 2;
#pragma unroll
    for (int mf = 0; mf < 2; mf++) {
        const int r = m0 + wm * 32 + mf * 16 + gid;
#pragma unroll
        for (int nf = 0; nf < 2; nf++) {
            const int cl = wn * 16 + nf * 8 + 2 * t4;
            const float* hp0 = ht + (size_t)r * HH + j0 + cl;
            const float* hp1 = hp0 + 8 * HH;
            float2 h0 = *(const float2*)hp0;
            float2 h1 = *(const float2*)hp1;

            float2 o0, o1;
            o0.x = gru1(acc[0][mf][nf][0] + bp[cl],     acc[1][mf][nf][0] + bp[64 + cl],
                        acc[2][mf][nf][0] + bp[128 + cl], acc[3][mf][nf][0] + bp[192 + cl], h0.x);
            o0.y = gru1(acc[0][mf][nf][1] + bp[cl + 1], acc[1][mf][nf][1] + bp[64 + cl + 1],
                        acc[2][mf][nf][1] + bp[128 + cl + 1], acc[3][mf][nf][1] + bp[192 + cl + 1], h0.y);
            o1.x = gru1(acc[0][mf][nf][2] + bp[cl],     acc[1][mf][nf][2] + bp[64 + cl],
                        acc[2][mf][nf][2] + bp[128 + cl], acc[3][mf][nf][2] + bp[192 + cl], h1.x);
            o1.y = gru1(acc[0][mf][nf][3] + bp[cl + 1], acc[1][mf][nf][3] + bp[64 + cl + 1],
                        acc[2][mf][nf][3] + bp[128 + cl + 1], acc[3][mf][nf][3] + bp[192 + cl + 1], h1.y);

            *(float2*)(out + (size_t)r * HH + j0 + cl)       = o0;
            *(float2*)(out + (size_t)(r + 8) * HH + j0 + cl) = o1;
        }
    }
}

// ---------------- launch ----------------------------------------------------
extern "C" void kernel_launch(void* const* d_in, const int* in_sizes, int n_in,
                              void* d_out, int out_size)
{
    const float* traj  = (const float*)d_in[0];
    const float* neigh = (const float*)d_in[1];
    const float* dist  = (const float*)d_in[2];
    const float* ht    = (const float*)d_in[3];
    const float* W_emb = (const float*)d_in[4];
    const float* b_emb = (const float*)d_in[5];
    const float* w_ih  = (const float*)d_in[6];
    const float* w_hh  = (const float*)d_in[7];
    const float* b_ih  = (const float*)d_in[8];
    const float* b_hh  = (const float*)d_in[9];
    const int*   starts = (const int*)d_in[10];
    float* out = (float*)d_out;

    float *p_traj_emb;
    __half *p_traj_h, *p_x_h, *p_wembT_h, *p_wembT2_h, *p_emb_h, *p_ht_h, *p_wih_h, *p_whh_h;
    int* p_sid;
    cudaGetSymbolAddress((void**)&p_traj_emb, g_traj_emb);
    cudaGetSymbolAddress((void**)&p_traj_h, g_traj_h);
    cudaGetSymbolAddress((void**)&p_x_h, g_x_h);
    cudaGetSymbolAddress((void**)&p_wembT_h, g_wembT_h);
    cudaGetSymbolAddress((void**)&p_wembT2_h, g_wembT2_h);
    cudaGetSymbolAddress((void**)&p_emb_h, g_emb_h);
    cudaGetSymbolAddress((void**)&p_ht_h, g_ht_h);
    cudaGetSymbolAddress((void**)&p_wih_h, g_wih_h);
    cudaGetSymbolAddress((void**)&p_whh_h, g_whh_h);
    cudaGetSymbolAddress((void**)&p_sid, g_sid);

    cudaFuncSetAttribute(fused_gru_kernel,
                         cudaFuncAttributeMaxDynamicSharedMemorySize, FG_SMEM);
    cudaFuncSetAttribute(emb_mma_kernel,
                         cudaFuncAttributeMaxDynamicSharedMemorySize, EM_SMEM);
    cudaFuncSetAttribute(h_gemm_kernel<512>,
                         cudaFuncAttributeMaxDynamicSharedMemorySize, ES_SMEM);

    // 1) merged prep (one launch)
    prep_kernel<<<PB7, 256>>>(traj, neigh, dist, ht, W_emb, w_ih, w_hh, starts,
                              p_traj_h, p_x_h, p_ht_h, p_wembT_h, p_wembT2_h,
                              p_wih_h, p_whh_h, p_sid);

    // 2) traj_emb(f32) = traj @ W_emb[64:576]   [HMMA]
    h_gemm_kernel<512><<<dim3(HH / 64, BDIM / 128), 256, ES_SMEM>>>(
        p_traj_h, p_wembT2_h, p_traj_emb);

    // 3) emb(f16) = relu(X @ WembT^T + traj_emb[sid] + b_emb)  [HMMA, 3-stage]
    emb_mma_kernel<<<dim3(HH / 64, NROWS / 128), 512, EM_SMEM>>>(
        p_x_h, p_wembT_h, p_traj_emb, b_emb, p_sid, p_emb_h);

    // 4) fused: gi/gh GEMMs (HMMA, batched-ldsm slices, cp.async) + gates
    fused_gru_kernel<<<dim3(HH / 64, NROWS / 128), 512, FG_SMEM>>>(
        p_emb_h, p_ht_h, p_wih_h, p_whh_h, ht, b_ih, b_hh, out);
}